// round 13
// baseline (speedup 1.0000x reference)
#include <cuda_runtime.h>

#define NEMB      512
#define QBLOCKS   256          // every block sorts 2 codewords
#define QTHREADS  512
#define CW_PER_BLOCK (NEMB / QBLOCKS)        // 2
#define LUT_SIZE  4096
#define LUT_CHUNK (LUT_SIZE / QTHREADS)      // 8 buckets per thread

__device__ float  g_sval[NEMB];
__device__ int    g_sidx[NEMB];
__device__ __align__(128) unsigned int g_rdy[QBLOCKS / 4];    // byte flags, 0/1
__device__ __align__(128) float2       g_loss_slot[QBLOCKS];  // (loss, flag)

__global__ void __launch_bounds__(QTHREADS, 2)
vq_fused_kernel(const float* __restrict__ x,
                const float* __restrict__ emb,
                float* __restrict__ out,
                int n, int write_loss) {
    __shared__ float s_emb[NEMB];
    __shared__ float sval[NEMB];
    __shared__ int   sidx[NEMB];
    __shared__ short lut[LUT_SIZE];
    __shared__ int   s_rank[CW_PER_BLOCK];
    __shared__ float s_loss;

    const int tid = threadIdx.x;
    const int bid = blockIdx.x;

    // ---- Prefetch this thread's 2 elements (independent of codebook) ------
    const int c    = bid * QTHREADS + tid;   // float2 chunk id
    const int base = c * 2;
    const bool full = (base + 1 < n);
    float2 v = make_float2(0.f, 0.f);
    if (full) v = *reinterpret_cast<const float2*>(x + base);

    // ---- Phase 1: EVERY block rank-sorts its 2 codewords ------------------
    if (tid < CW_PER_BLOCK) s_rank[tid] = 0;
    if (tid < NEMB / 4) {
        const float4 e = __ldg(&reinterpret_cast<const float4*>(emb)[tid]);
        reinterpret_cast<float4*>(s_emb)[tid] = e;
    }
    __syncthreads();

    {
        const int g  = tid >> 8;                         // 0..1 codeword group
        const int cw = bid * CW_PER_BLOCK + g;           // original index
        const int l  = tid & 255;                        // lane in group
        const float cv = s_emb[cw];
        const float2 e = reinterpret_cast<const float2*>(s_emb)[l];
        const int j = l * 2;
        int partial = 0;
        partial += (int)(e.x < cv) + (int)((e.x == cv) && (j + 0 < cw));
        partial += (int)(e.y < cv) + (int)((e.y == cv) && (j + 1 < cw));
        #pragma unroll
        for (int off = 16; off > 0; off >>= 1)
            partial += __shfl_xor_sync(0xFFFFFFFFu, partial, off);
        if ((tid & 31) == 0) atomicAdd(&s_rank[g], partial);
    }
    __syncthreads();

    if (tid < CW_PER_BLOCK) {
        const int mycw = bid * CW_PER_BLOCK + tid;
        const int r = s_rank[tid];             // exact permutation (keys unique)
        g_sval[r] = s_emb[mycw];
        g_sidx[r] = mycw;
        __threadfence();                       // publish entries before flag
    }
    __syncthreads();
    if (tid == 0) {
        // own-slot byte flag: no same-address contention
        ((volatile unsigned char*)g_rdy)[bid] = 1;
    }

    // ---- Phase 2: wait until ALL blocks published (read-only poll) --------
    if (tid == 0) {
        const uint4* f4 = reinterpret_cast<const uint4*>(g_rdy);
        for (;;) {
            unsigned int acc = 0xFFFFFFFFu;
            #pragma unroll
            for (int i = 0; i < QBLOCKS / 16; i++) {     // 16 x LDG.128
                const uint4 f = __ldcg(&f4[i]);
                acc &= f.x; acc &= f.y; acc &= f.z; acc &= f.w;
            }
            if (acc == 0x01010101u) break;
            __nanosleep(32);
            asm volatile("" ::: "memory");
        }
        s_loss = 0.0f;
    }
    __syncthreads();

    // Vectorized copy of sorted codebook from L2 (the coherence point).
    if (tid < NEMB / 4) {
        const float4 vv = __ldcg(&reinterpret_cast<const float4*>(g_sval)[tid]);
        reinterpret_cast<float4*>(sval)[tid] = vv;
    } else if (tid < NEMB / 2) {
        const int t = tid - NEMB / 4;
        const int4 ii = __ldcg(&reinterpret_cast<const int4*>(g_sidx)[t]);
        reinterpret_cast<int4*>(sidx)[t] = ii;
    }
    __syncthreads();

    // ---- Build bucket LUT: lut[k] = lower_bound(sval, edge_k) -------------
    const float vmin = sval[0];
    const float vmax = sval[NEMB - 1];
    const float rng  = vmax - vmin;
    const float inv  = (rng > 0.0f) ? (float)LUT_SIZE / rng : 0.0f;
    const float step = (rng > 0.0f) ? rng / (float)LUT_SIZE : 0.0f;

    {
        const int k0 = tid * LUT_CHUNK;
        const float edge0 = vmin + (float)k0 * step;
        int lo = 0, hi = NEMB;
        #pragma unroll
        for (int it = 0; it < 10; it++) {
            const int mid = (lo + hi) >> 1;
            if (hi > lo) { if (sval[mid] < edge0) lo = mid + 1; else hi = mid; }
        }
        #pragma unroll
        for (int j = 0; j < LUT_CHUNK; j++) {
            const float edge = vmin + (float)(k0 + j) * step;
            while (lo < NEMB && sval[lo] < edge) lo++;
            lut[k0 + j] = (short)lo;
        }
    }
    __syncthreads();

    // ---- Quantize: bucket start + short upward scan to true lower_bound ---
    float local = 0.0f;

    if (full) {
        float vv[2] = {v.x, v.y};
        float qq[2];
        #pragma unroll
        for (int e = 0; e < 2; e++) {
            const float xv = vv[e];
            int k = (int)((xv - vmin) * inv);
            k = min(max(k - 1, 0), LUT_SIZE - 1);   // -1: margin vs fp rounding
            int lo = (int)lut[k];
            while (lo < NEMB && sval[lo] < xv) lo++;

            float q, d2;
            if (lo == 0) {
                q = sval[0];
                const float d = __fadd_rn(xv, -q);
                d2 = __fmul_rn(d, d);
            } else if (lo == NEMB) {
                q = sval[NEMB - 1];
                const float d = __fadd_rn(xv, -q);
                d2 = __fmul_rn(d, d);
            } else {
                const float a  = sval[lo - 1];
                const float b  = sval[lo];
                const float da = __fadd_rn(xv, -a);
                const float db = __fadd_rn(xv, -b);
                const float da2 = __fmul_rn(da, da);
                const float db2 = __fmul_rn(db, db);
                bool pick_a;
                if (da2 < db2)      pick_a = true;
                else if (db2 < da2) pick_a = false;
                else                pick_a = (sidx[lo - 1] < sidx[lo]);
                q  = pick_a ? a   : b;
                d2 = pick_a ? da2 : db2;
            }
            qq[e] = q;
            local += d2;
        }
        float2 o;
        o.x = qq[0]; o.y = qq[1];
        *reinterpret_cast<float2*>(out + base) = o;
    } else {
        for (int i = base; i < n && i < base + 2; i++) {
            const float xv = x[i];
            int k = (int)((xv - vmin) * inv);
            k = min(max(k - 1, 0), LUT_SIZE - 1);
            int lo = (int)lut[k];
            while (lo < NEMB && sval[lo] < xv) lo++;
            float q, d2;
            if (lo == 0) {
                q = sval[0];
                const float d = __fadd_rn(xv, -q); d2 = __fmul_rn(d, d);
            } else if (lo == NEMB) {
                q = sval[NEMB - 1];
                const float d = __fadd_rn(xv, -q); d2 = __fmul_rn(d, d);
            } else {
                const float a  = sval[lo - 1];
                const float b  = sval[lo];
                const float da = __fadd_rn(xv, -a);
                const float db = __fadd_rn(xv, -b);
                const float da2 = __fmul_rn(da, da);
                const float db2 = __fmul_rn(db, db);
                bool pick_a;
                if (da2 < db2)      pick_a = true;
                else if (db2 < da2) pick_a = false;
                else                pick_a = (sidx[lo - 1] < sidx[lo]);
                q  = pick_a ? a   : b;
                d2 = pick_a ? da2 : db2;
            }
            out[i] = q;
            local += d2;
        }
    }

    // ---- Block loss: shuffle + smem atomic, then ONE own-slot store -------
    #pragma unroll
    for (int off = 16; off > 0; off >>= 1)
        local += __shfl_xor_sync(0xFFFFFFFFu, local, off);
    if ((tid & 31) == 0)
        atomicAdd(&s_loss, local);
    __syncthreads();

    if (tid == 0) {
        // single aligned 8B store: loss value + flag published atomically
        __stcg(&g_loss_slot[bid], make_float2(s_loss, 1.0f));
    }

    // ---- Phase 3: block 0 finalizes (poll own slot each) + resets state ---
    if (bid == 0) {
        __syncthreads();
        if (tid == 0) s_loss = 0.0f;
        __syncthreads();

        float myloss = 0.0f;
        if (tid < QBLOCKS) {
            float2 s;
            for (;;) {
                s = __ldcg(&g_loss_slot[tid]);
                if (s.y != 0.0f) break;
                __nanosleep(32);
                asm volatile("" ::: "memory");
            }
            myloss = s.x;
        }
        #pragma unroll
        for (int off = 16; off > 0; off >>= 1)
            myloss += __shfl_xor_sync(0xFFFFFFFFu, myloss, off);
        if ((tid & 31) == 0 && tid < QBLOCKS)
            atomicAdd(&s_loss, myloss);
        __syncthreads();

        if (tid == 0 && write_loss)
            out[n] = 1.25f * s_loss / (float)n;

        // Reset flags/slots for the next graph replay (visible at kernel end).
        if (tid < QBLOCKS)
            g_loss_slot[tid] = make_float2(0.0f, 0.0f);
        if (tid < QBLOCKS / 16)
            reinterpret_cast<uint4*>(g_rdy)[tid] = make_uint4(0u, 0u, 0u, 0u);
    }
}

extern "C" void kernel_launch(void* const* d_in, const int* in_sizes, int n_in,
                              void* d_out, int out_size) {
    const float* x   = (const float*)d_in[0];   // pre_quantized, 16*1*128*128
    const float* emb = (const float*)d_in[1];   // emb_weight, 512*1
    float* out = (float*)d_out;

    const int n = in_sizes[0];                  // 262144
    const int write_loss = (out_size > n) ? 1 : 0;

    vq_fused_kernel<<<QBLOCKS, QTHREADS>>>(x, emb, out, n, write_loss);
}

// round 14
// speedup vs baseline: 2.5194x; 2.5194x over previous
#include <cuda_runtime.h>

#define NEMB      512
#define QBLOCKS   256          // every block sorts 2 codewords
#define QTHREADS  512
#define CW_PER_BLOCK (NEMB / QBLOCKS)        // 2
#define LUT_SIZE  4096
#define LUT_CHUNK (LUT_SIZE / QTHREADS)      // 8 buckets per thread
#define NGRP      8                          // 8-way spread for global chains
#define GSTRIDE   32                         // 32 ints = 128 B between counters

__device__ float  g_sval[NEMB];
__device__ int    g_sidx[NEMB];
__device__ unsigned int          g_rdy1[NGRP * GSTRIDE];   // level-1 ready counters
__device__ unsigned int          g_rdy2;                    // level-2
__device__ volatile unsigned int g_all_ready;               // single poll word
__device__ float                 g_lossAcc[NGRP * GSTRIDE]; // 8-way loss partials
__device__ unsigned int          g_done1[NGRP * GSTRIDE];
__device__ unsigned int          g_done2;

__global__ void __launch_bounds__(QTHREADS, 2)
vq_fused_kernel(const float* __restrict__ x,
                const float* __restrict__ emb,
                float* __restrict__ out,
                int n, int write_loss) {
    __shared__ float s_emb[NEMB];
    __shared__ float sval[NEMB];
    __shared__ int   sidx[NEMB];
    __shared__ short lut[LUT_SIZE];
    __shared__ int   s_rank[CW_PER_BLOCK];
    __shared__ float s_loss;

    const int tid = threadIdx.x;
    const int bid = blockIdx.x;
    const int grp = bid & (NGRP - 1);

    // ---- Prefetch this thread's 2 elements (independent of codebook) ------
    const int c    = bid * QTHREADS + tid;   // float2 chunk id
    const int base = c * 2;
    const bool full = (base + 1 < n);
    float2 v = make_float2(0.f, 0.f);
    if (full) v = *reinterpret_cast<const float2*>(x + base);

    // ---- Phase 1: EVERY block rank-sorts its 2 codewords ------------------
    if (tid < CW_PER_BLOCK) s_rank[tid] = 0;
    if (tid < NEMB / 4) {
        const float4 e = __ldg(&reinterpret_cast<const float4*>(emb)[tid]);
        reinterpret_cast<float4*>(s_emb)[tid] = e;
    }
    __syncthreads();

    {
        const int g  = tid >> 8;                         // 0..1 codeword group
        const int cw = bid * CW_PER_BLOCK + g;           // original index
        const int l  = tid & 255;                        // lane in group
        const float cv = s_emb[cw];
        const float2 e = reinterpret_cast<const float2*>(s_emb)[l];
        const int j = l * 2;
        int partial = 0;
        partial += (int)(e.x < cv) + (int)((e.x == cv) && (j + 0 < cw));
        partial += (int)(e.y < cv) + (int)((e.y == cv) && (j + 1 < cw));
        #pragma unroll
        for (int off = 16; off > 0; off >>= 1)
            partial += __shfl_xor_sync(0xFFFFFFFFu, partial, off);
        if ((tid & 31) == 0) atomicAdd(&s_rank[g], partial);
    }
    __syncthreads();

    if (tid < CW_PER_BLOCK) {
        const int mycw = bid * CW_PER_BLOCK + tid;
        const int r = s_rank[tid];             // exact permutation (keys unique)
        g_sval[r] = s_emb[mycw];
        g_sidx[r] = mycw;
        __threadfence();                       // publish entries before flag
    }
    __syncthreads();

    // ---- Ready barrier: 8-way level-1 chains -> level-2 -> one poll word --
    if (tid == 0) {
        const unsigned r = atomicAdd(&g_rdy1[grp * GSTRIDE], 1u);
        if (r == (QBLOCKS / NGRP) - 1) {               // last in group
            const unsigned r2 = atomicAdd(&g_rdy2, 1u);
            if (r2 == NGRP - 1)
                g_all_ready = 1u;                      // volatile store
        }
        while (g_all_ready == 0u) { }                  // single-word spin
        s_loss = 0.0f;
    }
    __syncthreads();

    // Vectorized copy of sorted codebook from L2 (the coherence point).
    if (tid < NEMB / 4) {
        const float4 vv = __ldcg(&reinterpret_cast<const float4*>(g_sval)[tid]);
        reinterpret_cast<float4*>(sval)[tid] = vv;
    } else if (tid < NEMB / 2) {
        const int t = tid - NEMB / 4;
        const int4 ii = __ldcg(&reinterpret_cast<const int4*>(g_sidx)[t]);
        reinterpret_cast<int4*>(sidx)[t] = ii;
    }
    __syncthreads();

    // ---- Build bucket LUT: lut[k] = lower_bound(sval, edge_k) -------------
    const float vmin = sval[0];
    const float vmax = sval[NEMB - 1];
    const float rng  = vmax - vmin;
    const float inv  = (rng > 0.0f) ? (float)LUT_SIZE / rng : 0.0f;
    const float step = (rng > 0.0f) ? rng / (float)LUT_SIZE : 0.0f;

    {
        const int k0 = tid * LUT_CHUNK;
        const float edge0 = vmin + (float)k0 * step;
        int lo = 0, hi = NEMB;
        #pragma unroll
        for (int it = 0; it < 10; it++) {
            const int mid = (lo + hi) >> 1;
            if (hi > lo) { if (sval[mid] < edge0) lo = mid + 1; else hi = mid; }
        }
        #pragma unroll
        for (int j = 0; j < LUT_CHUNK; j++) {
            const float edge = vmin + (float)(k0 + j) * step;
            while (lo < NEMB && sval[lo] < edge) lo++;
            lut[k0 + j] = (short)lo;
        }
    }
    __syncthreads();

    // ---- Quantize: bucket start + short upward scan to true lower_bound ---
    float local = 0.0f;

    if (full) {
        float vv[2] = {v.x, v.y};
        float qq[2];
        #pragma unroll
        for (int e = 0; e < 2; e++) {
            const float xv = vv[e];
            int k = (int)((xv - vmin) * inv);
            k = min(max(k - 1, 0), LUT_SIZE - 1);   // -1: margin vs fp rounding
            int lo = (int)lut[k];
            while (lo < NEMB && sval[lo] < xv) lo++;

            float q, d2;
            if (lo == 0) {
                q = sval[0];
                const float d = __fadd_rn(xv, -q);
                d2 = __fmul_rn(d, d);
            } else if (lo == NEMB) {
                q = sval[NEMB - 1];
                const float d = __fadd_rn(xv, -q);
                d2 = __fmul_rn(d, d);
            } else {
                const float a  = sval[lo - 1];
                const float b  = sval[lo];
                const float da = __fadd_rn(xv, -a);
                const float db = __fadd_rn(xv, -b);
                const float da2 = __fmul_rn(da, da);
                const float db2 = __fmul_rn(db, db);
                bool pick_a;
                if (da2 < db2)      pick_a = true;
                else if (db2 < da2) pick_a = false;
                else                pick_a = (sidx[lo - 1] < sidx[lo]);
                q  = pick_a ? a   : b;
                d2 = pick_a ? da2 : db2;
            }
            qq[e] = q;
            local += d2;
        }
        float2 o;
        o.x = qq[0]; o.y = qq[1];
        *reinterpret_cast<float2*>(out + base) = o;
    } else {
        for (int i = base; i < n && i < base + 2; i++) {
            const float xv = x[i];
            int k = (int)((xv - vmin) * inv);
            k = min(max(k - 1, 0), LUT_SIZE - 1);
            int lo = (int)lut[k];
            while (lo < NEMB && sval[lo] < xv) lo++;
            float q, d2;
            if (lo == 0) {
                q = sval[0];
                const float d = __fadd_rn(xv, -q); d2 = __fmul_rn(d, d);
            } else if (lo == NEMB) {
                q = sval[NEMB - 1];
                const float d = __fadd_rn(xv, -q); d2 = __fmul_rn(d, d);
            } else {
                const float a  = sval[lo - 1];
                const float b  = sval[lo];
                const float da = __fadd_rn(xv, -a);
                const float db = __fadd_rn(xv, -b);
                const float da2 = __fmul_rn(da, da);
                const float db2 = __fmul_rn(db, db);
                bool pick_a;
                if (da2 < db2)      pick_a = true;
                else if (db2 < da2) pick_a = false;
                else                pick_a = (sidx[lo - 1] < sidx[lo]);
                q  = pick_a ? a   : b;
                d2 = pick_a ? da2 : db2;
            }
            out[i] = q;
            local += d2;
        }
    }

    // ---- Loss reduction -----------------------------------------------------
    #pragma unroll
    for (int off = 16; off > 0; off >>= 1)
        local += __shfl_xor_sync(0xFFFFFFFFu, local, off);
    if ((tid & 31) == 0)
        atomicAdd(&s_loss, local);
    __syncthreads();

    // ---- Done barrier: 8-way chains; 8th group-leader finalizes + resets --
    if (tid == 0) {
        atomicAdd(&g_lossAcc[grp * GSTRIDE], s_loss);
        __threadfence();                        // loss visible before done count
        const unsigned d = atomicAdd(&g_done1[grp * GSTRIDE], 1u);
        if (d == (QBLOCKS / NGRP) - 1) {
            const unsigned d2 = atomicAdd(&g_done2, 1u);
            if (d2 == NGRP - 1) {
                // All 256 blocks' loss atomics are complete and visible.
                float total = 0.0f;
                #pragma unroll
                for (int i = 0; i < NGRP; i++)
                    total += __ldcg(&g_lossAcc[i * GSTRIDE]);
                if (write_loss)
                    out[n] = 1.25f * total / (float)n;
                // Reset for next graph replay (all other blocks are past
                // every read of this state).
                #pragma unroll
                for (int i = 0; i < NGRP; i++) {
                    g_rdy1[i * GSTRIDE]   = 0u;
                    g_done1[i * GSTRIDE]  = 0u;
                    g_lossAcc[i * GSTRIDE] = 0.0f;
                }
                g_rdy2 = 0u;
                g_done2 = 0u;
                g_all_ready = 0u;
            }
        }
    }
}

extern "C" void kernel_launch(void* const* d_in, const int* in_sizes, int n_in,
                              void* d_out, int out_size) {
    const float* x   = (const float*)d_in[0];   // pre_quantized, 16*1*128*128
    const float* emb = (const float*)d_in[1];   // emb_weight, 512*1
    float* out = (float*)d_out;

    const int n = in_sizes[0];                  // 262144
    const int write_loss = (out_size > n) ? 1 : 0;

    vq_fused_kernel<<<QBLOCKS, QTHREADS>>>(x, emb, out, n, write_loss);
}